// round 3
// baseline (speedup 1.0000x reference)
#include <cuda_runtime.h>

#define NN   100000
#define NE   1600000
#define NPAD 100096          // 782 * 128, GEMM grids need no edge guards
#define D_IN  128
#define D_HID 256

// ---------------- scratch (static __device__ arrays; no allocation) --------
__device__ int   g_cnt[NN];
__device__ int   g_rowptr[NN + 1];
__device__ int   g_wp[NN];
__device__ int   g_col[NE];
__device__ float g_dinv[NN];
__device__ int   g_bsum[128];
__device__ __align__(16) float g_xa[(size_t)NPAD * D_IN];    // A@x
__device__ __align__(16) float g_h1[(size_t)NPAD * D_HID];   // relu(xa@W1+b1)
__device__ __align__(16) float g_y [(size_t)NPAD * D_IN];    // h1@W2

// ---------------- CSR build ------------------------------------------------
// edge_index is int32 (JAX default x64-disabled downcasts the int64 request).
__global__ void k_zero() {
    int i = blockIdx.x * blockDim.x + threadIdx.x;
    if (i < NN) g_cnt[i] = 0;
}

__global__ void k_hist(const int* __restrict__ ei) {
    int e = blockIdx.x * blockDim.x + threadIdx.x;
    if (e < NE) atomicAdd(&g_cnt[ei[NE + e]], 1);
}

__global__ void k_scan() {
    __shared__ int sh[1024];
    int i = blockIdx.x * 1024 + threadIdx.x;
    int v = (i < NN) ? g_cnt[i] : 0;
    sh[threadIdx.x] = v;
    __syncthreads();
    for (int off = 1; off < 1024; off <<= 1) {
        int t = (threadIdx.x >= off) ? sh[threadIdx.x - off] : 0;
        __syncthreads();
        sh[threadIdx.x] += t;
        __syncthreads();
    }
    if (i < NN) g_rowptr[i] = sh[threadIdx.x] - v;      // exclusive within block
    if (threadIdx.x == 1023) g_bsum[blockIdx.x] = sh[1023];
}

__global__ void k_scansum(int nb) {
    int acc = 0;
    for (int b = 0; b < nb; b++) { int v = g_bsum[b]; g_bsum[b] = acc; acc += v; }
}

__global__ void k_final() {
    int i = blockIdx.x * blockDim.x + threadIdx.x;
    if (i < NN) {
        int rp = g_rowptr[i] + g_bsum[i >> 10];
        g_rowptr[i] = rp;
        g_wp[i] = rp;
        g_dinv[i] = rsqrtf((float)(g_cnt[i] + 1));      // in-degree + self-loop
    }
    if (i == 0) g_rowptr[NN] = NE;
}

__global__ void k_fill(const int* __restrict__ ei) {
    int e = blockIdx.x * blockDim.x + threadIdx.x;
    if (e < NE) {
        int s = ei[e];
        int d = ei[NE + e];
        int pos = atomicAdd(&g_wp[d], 1);
        g_col[pos] = s;
    }
}

// ---------------- aggregation (one warp per node, 128-dim rows) ------------
// acc = dinv[d] * ( sum_{s in nbrs(d)} dinv[s]*X[s] + dinv[d]*X[d] )
__device__ __forceinline__ float4 agg_row(const float* __restrict__ X,
                                          int node, int lane) {
    const float4* Xv = (const float4*)X;
    float4 acc = make_float4(0.f, 0.f, 0.f, 0.f);
    int r0 = g_rowptr[node], r1 = g_rowptr[node + 1];
    float di = g_dinv[node];

#pragma unroll 4
    for (int j = r0; j < r1; j++) {
        int s = g_col[j];
        float w = g_dinv[s];
        float4 v = Xv[(size_t)s * 32 + lane];
        acc.x += v.x * w; acc.y += v.y * w; acc.z += v.z * w; acc.w += v.w * w;
    }
    float4 v = Xv[(size_t)node * 32 + lane];   // self-loop
    acc.x = (acc.x + v.x * di) * di;
    acc.y = (acc.y + v.y * di) * di;
    acc.z = (acc.z + v.z * di) * di;
    acc.w = (acc.w + v.w * di) * di;
    return acc;
}

// xa = A @ x
__global__ void k_agg1(const float* __restrict__ x) {
    int gw   = (blockIdx.x * blockDim.x + threadIdx.x) >> 5;
    int lane = threadIdx.x & 31;
    if (gw >= NN) return;
    float4 acc = agg_row(x, gw, lane);
    ((float4*)g_xa)[(size_t)gw * 32 + lane] = acc;
}

// out = LayerNorm(A @ y + b2)
__global__ void k_agg2(float* __restrict__ out,
                       const float* __restrict__ bias,
                       const float* __restrict__ gamma,
                       const float* __restrict__ beta) {
    int gw   = (blockIdx.x * blockDim.x + threadIdx.x) >> 5;
    int lane = threadIdx.x & 31;
    if (gw >= NN) return;
    float4 acc = agg_row(g_y, gw, lane);

    float4 bb = ((const float4*)bias)[lane];
    acc.x += bb.x; acc.y += bb.y; acc.z += bb.z; acc.w += bb.w;

    float s = acc.x + acc.y + acc.z + acc.w;
#pragma unroll
    for (int o = 16; o; o >>= 1) s += __shfl_xor_sync(0xffffffffu, s, o);
    float mu = s * (1.f / 128.f);

    float d0 = acc.x - mu, d1 = acc.y - mu, d2 = acc.z - mu, d3 = acc.w - mu;
    float ss = d0 * d0 + d1 * d1 + d2 * d2 + d3 * d3;
#pragma unroll
    for (int o = 16; o; o >>= 1) ss += __shfl_xor_sync(0xffffffffu, ss, o);
    float rs = rsqrtf(ss * (1.f / 128.f) + 1e-5f);

    float4 g  = ((const float4*)gamma)[lane];
    float4 be = ((const float4*)beta)[lane];
    float4 o4;
    o4.x = d0 * rs * g.x + be.x;
    o4.y = d1 * rs * g.y + be.y;
    o4.z = d2 * rs * g.z + be.z;
    o4.w = d3 * rs * g.w + be.w;
    ((float4*)out)[(size_t)gw * 32 + lane] = o4;
}

// ---------------- SGEMM 128x128 tile, 8x8 thread tile, double-buffered -----
// C[M,N] = A[M,K] @ B[K,N] (+bias+relu). Compile-time N, K. M padded.
template <int N, int K, bool BIAS_RELU>
__device__ __forceinline__ void sgemm_body(const float* __restrict__ A,
                                           const float* __restrict__ B,
                                           const float* __restrict__ bias,
                                           float* __restrict__ C) {
    __shared__ float As[2][8][128];
    __shared__ float Bs[2][8][128];

    int tid  = threadIdx.x;
    int trow = tid >> 4;          // 0..15
    int tcol = tid & 15;          // 0..15
    int aRow = tid >> 1;          // 0..127
    int aCol = (tid & 1) * 4;     // 0 or 4
    int bRow = tid >> 5;          // 0..7
    int bCol = (tid & 31) * 4;    // 0..124

    const float* Ap = A + (size_t)(blockIdx.y * 128 + aRow) * K + aCol;
    const float* Bp = B + (size_t)bRow * N + blockIdx.x * 128 + bCol;

    float4 a4 = *(const float4*)Ap;
    float4 b4 = *(const float4*)Bp;
    As[0][aCol + 0][aRow] = a4.x; As[0][aCol + 1][aRow] = a4.y;
    As[0][aCol + 2][aRow] = a4.z; As[0][aCol + 3][aRow] = a4.w;
    *(float4*)&Bs[0][bRow][bCol] = b4;
    __syncthreads();

    float acc[8][8];
#pragma unroll
    for (int i = 0; i < 8; i++)
#pragma unroll
        for (int j = 0; j < 8; j++) acc[i][j] = 0.f;

    const int nT = K >> 3;
    int buf = 0;
#pragma unroll 1
    for (int t = 0; t < nT; t++) {
        if (t + 1 < nT) {
            a4 = *(const float4*)(Ap + (t + 1) * 8);
            b4 = *(const float4*)(Bp + (size_t)(t + 1) * 8 * N);
        }
#pragma unroll
        for (int k = 0; k < 8; k++) {
            float4 ra0 = *(const float4*)&As[buf][k][trow * 8];
            float4 ra1 = *(const float4*)&As[buf][k][trow * 8 + 4];
            float4 rb0 = *(const float4*)&Bs[buf][k][tcol * 8];
            float4 rb1 = *(const float4*)&Bs[buf][k][tcol * 8 + 4];
            float ra[8] = {ra0.x, ra0.y, ra0.z, ra0.w, ra1.x, ra1.y, ra1.z, ra1.w};
            float rb[8] = {rb0.x, rb0.y, rb0.z, rb0.w, rb1.x, rb1.y, rb1.z, rb1.w};
#pragma unroll
            for (int i = 0; i < 8; i++)
#pragma unroll
                for (int j = 0; j < 8; j++) acc[i][j] += ra[i] * rb[j];
        }
        if (t + 1 < nT) {
            int nb = buf ^ 1;
            As[nb][aCol + 0][aRow] = a4.x; As[nb][aCol + 1][aRow] = a4.y;
            As[nb][aCol + 2][aRow] = a4.z; As[nb][aCol + 3][aRow] = a4.w;
            *(float4*)&Bs[nb][bRow][bCol] = b4;
            __syncthreads();
            buf = nb;
        }
    }

    int ccol = blockIdx.x * 128 + tcol * 8;
    float bv[8];
    if (BIAS_RELU) {
#pragma unroll
        for (int j = 0; j < 8; j++) bv[j] = bias[ccol + j];
    }
    float* Cp = C + (size_t)(blockIdx.y * 128 + trow * 8) * N + ccol;
#pragma unroll
    for (int i = 0; i < 8; i++) {
        float4 o1, o2;
        if (BIAS_RELU) {
            o1.x = fmaxf(acc[i][0] + bv[0], 0.f);
            o1.y = fmaxf(acc[i][1] + bv[1], 0.f);
            o1.z = fmaxf(acc[i][2] + bv[2], 0.f);
            o1.w = fmaxf(acc[i][3] + bv[3], 0.f);
            o2.x = fmaxf(acc[i][4] + bv[4], 0.f);
            o2.y = fmaxf(acc[i][5] + bv[5], 0.f);
            o2.z = fmaxf(acc[i][6] + bv[6], 0.f);
            o2.w = fmaxf(acc[i][7] + bv[7], 0.f);
        } else {
            o1.x = acc[i][0]; o1.y = acc[i][1]; o1.z = acc[i][2]; o1.w = acc[i][3];
            o2.x = acc[i][4]; o2.y = acc[i][5]; o2.z = acc[i][6]; o2.w = acc[i][7];
        }
        *(float4*)(Cp)     = o1;
        *(float4*)(Cp + 4) = o2;
        Cp += N;
    }
}

// h1 = relu(xa @ W1 + b1)   [NPAD,256]
__global__ __launch_bounds__(256)
void k_sgemm1(const float* __restrict__ W1, const float* __restrict__ b1) {
    sgemm_body<D_HID, D_IN, true>(g_xa, W1, b1, g_h1);
}

// y = h1 @ W2               [NPAD,128]
__global__ __launch_bounds__(256)
void k_sgemm2(const float* __restrict__ W2) {
    sgemm_body<D_IN, D_HID, false>(g_h1, W2, nullptr, g_y);
}

// ---------------- launch (kernel launches ONLY) -----------------------------
extern "C" void kernel_launch(void* const* d_in, const int* in_sizes, int n_in,
                              void* d_out, int out_size) {
    const float* x     = (const float*)d_in[0];
    const int*   ei    = (const int*)d_in[1];      // int32 edge_index [2, NE]
    const float* W1    = (const float*)d_in[2];
    const float* b1    = (const float*)d_in[3];
    const float* W2    = (const float*)d_in[4];
    const float* b2    = (const float*)d_in[5];
    const float* gamma = (const float*)d_in[6];
    const float* beta  = (const float*)d_in[7];
    float* out = (float*)d_out;

    // CSR build (shared by both aggregations)
    k_zero   <<<(NN + 255) / 256, 256>>>();
    k_hist   <<<(NE + 255) / 256, 256>>>(ei);
    k_scan   <<<98, 1024>>>();
    k_scansum<<<1, 1>>>(98);
    k_final  <<<(NN + 255) / 256, 256>>>();
    k_fill   <<<(NE + 255) / 256, 256>>>(ei);

    // xa = A @ x  (128-d aggregation)
    k_agg1<<<(NN * 32) / 256, 256>>>(x);

    // h1 = relu(xa @ W1 + b1)
    dim3 g1(D_HID / 128, NPAD / 128);
    k_sgemm1<<<g1, 256>>>(W1, b1);

    // y = h1 @ W2
    dim3 g2(D_IN / 128, NPAD / 128);
    k_sgemm2<<<g2, 256>>>(W2);

    // out = LayerNorm(A @ y + b2)
    k_agg2<<<(NN * 32) / 256, 256>>>(out, b2, gamma, beta);
}

// round 6
// speedup vs baseline: 1.5778x; 1.5778x over previous
#include <cuda_runtime.h>
#include <cstdint>

#define NN   100000
#define NE   1600000
#define NPAD 100096          // 782 * 128
#define D_IN  128
#define D_HID 256
#define NTILES (NPAD / 128)  // 782

// ---------------- scratch (static __device__ arrays; no allocation) --------
// NOTE: these are ONLY referenced from device code (host-side symbol address
// is invalid and cudaGetSymbolAddress is banned by the harness).
__device__ int   g_cnt[NN];
__device__ int   g_rowptr[NN + 1];
__device__ int   g_wp[NN];
__device__ int   g_col[NE];
__device__ float g_dinv[NN];
__device__ int   g_bsum[128];
__device__ __align__(16) float g_xa[(size_t)NPAD * D_IN];    // A@x
__device__ __align__(16) float g_h1[(size_t)NPAD * D_HID];   // relu(xa@W1+b1)
__device__ __align__(16) float g_y [(size_t)NPAD * D_IN];    // h1@W2

// ---------------- CSR build ------------------------------------------------
__global__ void k_zero() {
    int i = blockIdx.x * blockDim.x + threadIdx.x;
    if (i < NN) g_cnt[i] = 0;
}
__global__ void k_hist(const int* __restrict__ ei) {
    int e = blockIdx.x * blockDim.x + threadIdx.x;
    if (e < NE) atomicAdd(&g_cnt[ei[NE + e]], 1);
}
__global__ void k_scan() {
    __shared__ int sh[1024];
    int i = blockIdx.x * 1024 + threadIdx.x;
    int v = (i < NN) ? g_cnt[i] : 0;
    sh[threadIdx.x] = v;
    __syncthreads();
    for (int off = 1; off < 1024; off <<= 1) {
        int t = (threadIdx.x >= off) ? sh[threadIdx.x - off] : 0;
        __syncthreads();
        sh[threadIdx.x] += t;
        __syncthreads();
    }
    if (i < NN) g_rowptr[i] = sh[threadIdx.x] - v;
    if (threadIdx.x == 1023) g_bsum[blockIdx.x] = sh[1023];
}
__global__ void k_scansum() {          // parallel 98-wide exclusive scan
    __shared__ int sh[128];
    int t = threadIdx.x;
    int v = (t < 98) ? g_bsum[t] : 0;
    sh[t] = v;
    __syncthreads();
    for (int off = 1; off < 128; off <<= 1) {
        int u = (t >= off) ? sh[t - off] : 0;
        __syncthreads();
        sh[t] += u;
        __syncthreads();
    }
    if (t < 98) g_bsum[t] = sh[t] - v;
}
__global__ void k_final() {
    int i = blockIdx.x * blockDim.x + threadIdx.x;
    if (i < NN) {
        int rp = g_rowptr[i] + g_bsum[i >> 10];
        g_rowptr[i] = rp;
        g_wp[i] = rp;
        g_dinv[i] = rsqrtf((float)(g_cnt[i] + 1));
    }
    if (i == 0) g_rowptr[NN] = NE;
}
__global__ void k_fill(const int* __restrict__ ei) {
    int e = blockIdx.x * blockDim.x + threadIdx.x;
    if (e < NE) {
        int s = ei[e];
        int d = ei[NE + e];
        int pos = atomicAdd(&g_wp[d], 1);
        g_col[pos] = s;
    }
}

// ---------------- aggregation (one warp per node, 128-dim rows) ------------
__device__ __forceinline__ float4 agg_row(const float* __restrict__ X,
                                          int node, int lane) {
    const float4* Xv = (const float4*)X;
    float4 acc = make_float4(0.f, 0.f, 0.f, 0.f);
    int r0 = g_rowptr[node], r1 = g_rowptr[node + 1];
    float di = g_dinv[node];
#pragma unroll 4
    for (int j = r0; j < r1; j++) {
        int s = g_col[j];
        float w = g_dinv[s];
        float4 v = Xv[(size_t)s * 32 + lane];
        acc.x += v.x * w; acc.y += v.y * w; acc.z += v.z * w; acc.w += v.w * w;
    }
    float4 v = Xv[(size_t)node * 32 + lane];
    acc.x = (acc.x + v.x * di) * di;
    acc.y = (acc.y + v.y * di) * di;
    acc.z = (acc.z + v.z * di) * di;
    acc.w = (acc.w + v.w * di) * di;
    return acc;
}

__global__ void k_agg1(const float* __restrict__ x) {
    int gw   = (blockIdx.x * blockDim.x + threadIdx.x) >> 5;
    int lane = threadIdx.x & 31;
    if (gw >= NN) return;
    ((float4*)g_xa)[(size_t)gw * 32 + lane] = agg_row(x, gw, lane);
}

__global__ void k_agg2(float* __restrict__ out,
                       const float* __restrict__ bias,
                       const float* __restrict__ gamma,
                       const float* __restrict__ beta) {
    int gw   = (blockIdx.x * blockDim.x + threadIdx.x) >> 5;
    int lane = threadIdx.x & 31;
    if (gw >= NN) return;
    float4 acc = agg_row(g_y, gw, lane);

    float4 bb = ((const float4*)bias)[lane];
    acc.x += bb.x; acc.y += bb.y; acc.z += bb.z; acc.w += bb.w;

    float s = acc.x + acc.y + acc.z + acc.w;
#pragma unroll
    for (int o = 16; o; o >>= 1) s += __shfl_xor_sync(0xffffffffu, s, o);
    float mu = s * (1.f / 128.f);

    float d0 = acc.x - mu, d1 = acc.y - mu, d2 = acc.z - mu, d3 = acc.w - mu;
    float ss = d0 * d0 + d1 * d1 + d2 * d2 + d3 * d3;
#pragma unroll
    for (int o = 16; o; o >>= 1) ss += __shfl_xor_sync(0xffffffffu, ss, o);
    float rs = rsqrtf(ss * (1.f / 128.f) + 1e-5f);

    float4 g  = ((const float4*)gamma)[lane];
    float4 be = ((const float4*)beta)[lane];
    float4 o4;
    o4.x = d0 * rs * g.x + be.x;
    o4.y = d1 * rs * g.y + be.y;
    o4.z = d2 * rs * g.z + be.z;
    o4.w = d3 * rs * g.w + be.w;
    ((float4*)out)[(size_t)gw * 32 + lane] = o4;
}

// ---------------- tf32 mma.sync GEMM ----------------------------------------
// C[128,NT-tile] = A[128,K] @ B[K,NT], fragments staged in mma register order.
// Frag layouts (u32):
//   Af[buf][(kstep*8 + mtile)*32 + lane][4]          (16B/lane  -> LDS.128)
//   Bf[buf][kstep*16*66 + ntile*66 + lane*2 + reg]   (8B/lane   -> LDS.64, pad 66)
#define BSTRIDE 66

__device__ __forceinline__ uint32_t cvt_tf32(float f) {
    uint32_t r; asm("cvt.rna.tf32.f32 %0, %1;" : "=r"(r) : "f"(f)); return r;
}

__device__ __forceinline__ void mma1688(float* c, const uint32_t* a, const uint32_t* b) {
    asm volatile(
        "mma.sync.aligned.m16n8k8.row.col.f32.tf32.tf32.f32 "
        "{%0,%1,%2,%3}, {%4,%5,%6,%7}, {%8,%9}, {%0,%1,%2,%3};"
        : "+f"(c[0]), "+f"(c[1]), "+f"(c[2]), "+f"(c[3])
        : "r"(a[0]), "r"(a[1]), "r"(a[2]), "r"(a[3]), "r"(b[0]), "r"(b[1]));
}

template <int K, int NT, bool BIAS_RELU>
__device__ __forceinline__ void mma_body(const float* __restrict__ A,
                                         const float* __restrict__ B,
                                         const float* __restrict__ bias,
                                         float* __restrict__ C) {
    __shared__ uint32_t Af[2][2048];          // 2 ksteps * 8 mtiles * 32 * 4
    __shared__ uint32_t Bf[2][2 * 16 * BSTRIDE];

    int tid  = threadIdx.x;
    int wid  = tid >> 5, lane = tid & 31;
    int wm   = wid >> 2, wn = wid & 3;        // 2x4 warp grid, 64x32 warp tile
    int rowBase = blockIdx.y * 128;
    int nBase   = blockIdx.x * 128;

    const float* Ab = A + (size_t)rowBase * K;
    const float* Bb = B + nBase;

    float acc[4][4][4];
#pragma unroll
    for (int i = 0; i < 4; i++)
#pragma unroll
        for (int j = 0; j < 4; j++)
#pragma unroll
            for (int q = 0; q < 4; q++) acc[i][j][q] = 0.f;

    float4 sa[2], sb[2];

    auto ldStage = [&](int ch) {
#pragma unroll
        for (int it = 0; it < 2; it++) {
            int i = tid + it * 256;           // 0..511
            int row = i >> 2, k4 = (i & 3) << 2;
            sa[it] = *(const float4*)(Ab + (size_t)row * K + ch * 16 + k4);
            int k = i >> 5, n4 = (i & 31) << 2;
            sb[it] = *(const float4*)(Bb + (size_t)(ch * 16 + k) * NT + n4);
        }
    };
    auto stStage = [&](uint32_t* af, uint32_t* bf) {
#pragma unroll
        for (int it = 0; it < 2; it++) {
            int i = tid + it * 256;
            {   // A element (row, k4+q)
                int row = i >> 2, k4 = (i & 3) << 2;
                int mtile = row >> 4, r = row & 15;
                const float* v = (const float*)&sa[it];
#pragma unroll
                for (int q = 0; q < 4; q++) {
                    int c = k4 + q, kstep = c >> 3, cc = c & 7;
                    int reg = ((r >> 3) & 1) | (((cc >> 2) & 1) << 1);
                    int ln  = (r & 7) * 4 + (cc & 3);
                    af[((kstep * 8 + mtile) * 32 + ln) * 4 + reg] = cvt_tf32(v[q]);
                }
            }
            {   // B element (k, n4+q)
                int k = i >> 5, n4 = (i & 31) << 2;
                int kstep = k >> 3, r = k & 7, reg = (r >> 2) & 1;
                const float* v = (const float*)&sb[it];
#pragma unroll
                for (int q = 0; q < 4; q++) {
                    int n = n4 + q, ntile = n >> 3;
                    int ln = (n & 7) * 4 + (r & 3);
                    bf[kstep * 16 * BSTRIDE + ntile * BSTRIDE + ln * 2 + reg] =
                        cvt_tf32(v[q]);
                }
            }
        }
    };

    const int nch = K >> 4;
    ldStage(0);
    stStage(Af[0], Bf[0]);
    __syncthreads();

#pragma unroll 1
    for (int ch = 0; ch < nch; ch++) {
        int buf = ch & 1;
        if (ch + 1 < nch) ldStage(ch + 1);    // LDG early, hide under mma

#pragma unroll
        for (int ks = 0; ks < 2; ks++) {
            uint32_t afr[4][4];
            uint32_t bfr[4][2];
#pragma unroll
            for (int i = 0; i < 4; i++) {
                int mtile = wm * 4 + i;
                *(uint4*)afr[i] =
                    *(const uint4*)&Af[buf][((ks * 8 + mtile) * 32 + lane) * 4];
            }
#pragma unroll
            for (int j = 0; j < 4; j++) {
                int ntile = wn * 4 + j;
                *(uint2*)bfr[j] =
                    *(const uint2*)&Bf[buf][ks * 16 * BSTRIDE + ntile * BSTRIDE + lane * 2];
            }
#pragma unroll
            for (int i = 0; i < 4; i++)
#pragma unroll
                for (int j = 0; j < 4; j++)
                    mma1688(acc[i][j], afr[i], bfr[j]);
        }

        if (ch + 1 < nch) stStage(Af[buf ^ 1], Bf[buf ^ 1]);
        __syncthreads();
    }

    // epilogue
    int crow = rowBase + wm * 64 + (lane >> 2);
    int ccol = nBase + wn * 32 + (lane & 3) * 2;
#pragma unroll
    for (int i = 0; i < 4; i++) {
#pragma unroll
        for (int j = 0; j < 4; j++) {
            int r0 = crow + i * 16, c0 = ccol + j * 8;
            float2 v0 = make_float2(acc[i][j][0], acc[i][j][1]);
            float2 v1 = make_float2(acc[i][j][2], acc[i][j][3]);
            if (BIAS_RELU) {
                float bx = bias[c0], by = bias[c0 + 1];
                v0.x = fmaxf(v0.x + bx, 0.f); v0.y = fmaxf(v0.y + by, 0.f);
                v1.x = fmaxf(v1.x + bx, 0.f); v1.y = fmaxf(v1.y + by, 0.f);
            }
            *(float2*)&C[(size_t)r0 * NT + c0]       = v0;
            *(float2*)&C[(size_t)(r0 + 8) * NT + c0] = v1;
        }
    }
}

// Wrappers: scratch symbols referenced from DEVICE code only.
__global__ __launch_bounds__(256)
void k_mma1(const float* __restrict__ W1, const float* __restrict__ b1) {
    mma_body<D_IN, D_HID, true>(g_xa, W1, b1, g_h1);
}
__global__ __launch_bounds__(256)
void k_mma2(const float* __restrict__ W2) {
    mma_body<D_HID, D_IN, false>(g_h1, W2, nullptr, g_y);
}

// ---------------- launch (kernel launches ONLY) -----------------------------
extern "C" void kernel_launch(void* const* d_in, const int* in_sizes, int n_in,
                              void* d_out, int out_size) {
    const float* x     = (const float*)d_in[0];
    const int*   ei    = (const int*)d_in[1];      // int32 edge_index [2, NE]
    const float* W1    = (const float*)d_in[2];
    const float* b1    = (const float*)d_in[3];
    const float* W2    = (const float*)d_in[4];
    const float* b2    = (const float*)d_in[5];
    const float* gamma = (const float*)d_in[6];
    const float* beta  = (const float*)d_in[7];
    float* out = (float*)d_out;

    // CSR build
    k_zero   <<<(NN + 255) / 256, 256>>>();
    k_hist   <<<(NE + 255) / 256, 256>>>(ei);
    k_scan   <<<98, 1024>>>();
    k_scansum<<<1, 128>>>();
    k_final  <<<(NN + 255) / 256, 256>>>();
    k_fill   <<<(NE + 255) / 256, 256>>>(ei);

    // xa = A @ x
    k_agg1<<<(NN * 32) / 256, 256>>>(x);

    // h1 = relu(xa @ W1 + b1)   (tf32 mma.sync)
    dim3 g1(D_HID / 128, NTILES);
    k_mma1<<<g1, 256>>>(W1, b1);

    // y = h1 @ W2               (tf32 mma.sync)
    dim3 g2(D_IN / 128, NTILES);
    k_mma2<<<g2, 256>>>(W2);

    // out = LayerNorm(A @ y + b2)
    k_agg2<<<(NN * 32) / 256, 256>>>(out, b2, gamma, beta);
}

// round 7
// speedup vs baseline: 1.5926x; 1.0094x over previous
#include <cuda_runtime.h>
#include <cuda_fp16.h>
#include <cstdint>

#define NN   100000
#define NE   1600000
#define NPAD 100096          // 782 * 128
#define D_IN  128
#define D_HID 256
#define NTILES (NPAD / 128)  // 782

// ---------------- scratch (static __device__ arrays; device-code refs only) -
__device__ int   g_cnt[NN];
__device__ int   g_rowptr[NN + 1];
__device__ int   g_wp[NN];
__device__ int   g_col[NE];
__device__ float g_dinv[NN];
__device__ int   g_bsum[128];
__device__ __align__(16) float  g_xa[(size_t)NPAD * D_IN];    // A@x (fp32)
__device__ __align__(16) __half g_xh[(size_t)NN   * D_IN];    // x as fp16
__device__ __align__(16) __half g_h1[(size_t)NPAD * D_HID];   // relu(xa@W1+b1)
__device__ __align__(16) __half g_y [(size_t)NPAD * D_IN];    // h1@W2

// ---------------- CSR build ------------------------------------------------
__global__ void k_zero() {
    int i = blockIdx.x * blockDim.x + threadIdx.x;
    if (i < NN) g_cnt[i] = 0;
}
__global__ void k_hist(const int* __restrict__ ei) {
    int e = blockIdx.x * blockDim.x + threadIdx.x;
    if (e < NE) atomicAdd(&g_cnt[ei[NE + e]], 1);
}
__global__ void k_scan() {
    __shared__ int sh[1024];
    int i = blockIdx.x * 1024 + threadIdx.x;
    int v = (i < NN) ? g_cnt[i] : 0;
    sh[threadIdx.x] = v;
    __syncthreads();
    for (int off = 1; off < 1024; off <<= 1) {
        int t = (threadIdx.x >= off) ? sh[threadIdx.x - off] : 0;
        __syncthreads();
        sh[threadIdx.x] += t;
        __syncthreads();
    }
    if (i < NN) g_rowptr[i] = sh[threadIdx.x] - v;      // block-local exclusive
    if (threadIdx.x == 1023) g_bsum[blockIdx.x] = sh[1023];
}
// k_final also scans the 98 block sums (redundantly per block) — saves a launch
__global__ void k_final() {
    __shared__ int shI[128];
    int t = threadIdx.x;
    if (t < 128) shI[t] = (t < 98) ? g_bsum[t] : 0;
    __syncthreads();
    for (int off = 1; off < 128; off <<= 1) {
        int u = (t >= off && t < 128) ? shI[t - off] : 0;
        __syncthreads();
        if (t < 128) shI[t] += u;
        __syncthreads();
    }
    int i = blockIdx.x * blockDim.x + t;
    if (i < NN) {
        int b = i >> 10;
        int base = (b == 0) ? 0 : shI[b - 1];
        int rp = g_rowptr[i] + base;
        g_rowptr[i] = rp;
        g_wp[i] = rp;
        g_dinv[i] = rsqrtf((float)(g_cnt[i] + 1));
    }
    if (i == 0) g_rowptr[NN] = NE;
}
__global__ void k_fill(const int* __restrict__ ei) {
    int e = blockIdx.x * blockDim.x + threadIdx.x;
    if (e < NE) {
        int s = ei[e];
        int d = ei[NE + e];
        int pos = atomicAdd(&g_wp[d], 1);
        g_col[pos] = s;
    }
}
// x (fp32) -> g_xh (fp16)
__global__ void k_cvt(const float* __restrict__ x) {
    int i = blockIdx.x * blockDim.x + threadIdx.x;   // one float4 each
    if (i < NN * 32) {
        float4 v = ((const float4*)x)[i];
        __half2 h0 = __floats2half2_rn(v.x, v.y);
        __half2 h1 = __floats2half2_rn(v.z, v.w);
        ((uint2*)g_xh)[i] = make_uint2(*(uint32_t*)&h0, *(uint32_t*)&h1);
    }
}

// ---------------- aggregation (one warp per node, fp16 rows, fp32 accum) ---
__device__ __forceinline__ float4 agg_row_h(const __half* __restrict__ X,
                                            int node, int lane) {
    const uint2* Xv = (const uint2*)X;              // 4 halves per lane
    float4 acc = make_float4(0.f, 0.f, 0.f, 0.f);
    int r0 = g_rowptr[node], r1 = g_rowptr[node + 1];
    float di = g_dinv[node];
#pragma unroll 4
    for (int j = r0; j < r1; j++) {
        int s = g_col[j];
        float w = g_dinv[s];
        uint2 raw = Xv[(size_t)s * 32 + lane];
        float2 f0 = __half22float2(*(__half2*)&raw.x);
        float2 f1 = __half22float2(*(__half2*)&raw.y);
        acc.x += f0.x * w; acc.y += f0.y * w;
        acc.z += f1.x * w; acc.w += f1.y * w;
    }
    uint2 raw = Xv[(size_t)node * 32 + lane];       // self-loop
    float2 f0 = __half22float2(*(__half2*)&raw.x);
    float2 f1 = __half22float2(*(__half2*)&raw.y);
    acc.x = (acc.x + f0.x * di) * di;
    acc.y = (acc.y + f0.y * di) * di;
    acc.z = (acc.z + f1.x * di) * di;
    acc.w = (acc.w + f1.y * di) * di;
    return acc;
}

__global__ void k_agg1() {
    int gw   = (blockIdx.x * blockDim.x + threadIdx.x) >> 5;
    int lane = threadIdx.x & 31;
    if (gw >= NN) return;
    ((float4*)g_xa)[(size_t)gw * 32 + lane] = agg_row_h(g_xh, gw, lane);
}

__global__ void k_agg2(float* __restrict__ out,
                       const float* __restrict__ bias,
                       const float* __restrict__ gamma,
                       const float* __restrict__ beta) {
    int gw   = (blockIdx.x * blockDim.x + threadIdx.x) >> 5;
    int lane = threadIdx.x & 31;
    if (gw >= NN) return;
    float4 acc = agg_row_h(g_y, gw, lane);

    float4 bb = ((const float4*)bias)[lane];
    acc.x += bb.x; acc.y += bb.y; acc.z += bb.z; acc.w += bb.w;

    float s = acc.x + acc.y + acc.z + acc.w;
#pragma unroll
    for (int o = 16; o; o >>= 1) s += __shfl_xor_sync(0xffffffffu, s, o);
    float mu = s * (1.f / 128.f);

    float d0 = acc.x - mu, d1 = acc.y - mu, d2 = acc.z - mu, d3 = acc.w - mu;
    float ss = d0 * d0 + d1 * d1 + d2 * d2 + d3 * d3;
#pragma unroll
    for (int o = 16; o; o >>= 1) ss += __shfl_xor_sync(0xffffffffu, ss, o);
    float rs = rsqrtf(ss * (1.f / 128.f) + 1e-5f);

    float4 g  = ((const float4*)gamma)[lane];
    float4 be = ((const float4*)beta)[lane];
    float4 o4;
    o4.x = d0 * rs * g.x + be.x;
    o4.y = d1 * rs * g.y + be.y;
    o4.z = d2 * rs * g.z + be.z;
    o4.w = d3 * rs * g.w + be.w;
    ((float4*)out)[(size_t)gw * 32 + lane] = o4;
}

// ---------------- tf32 mma.sync GEMM ----------------------------------------
// C[128,NT-tile] = A[128,K] @ B[K,NT]; A fp32 or fp16, C written as fp16.
//   Af[buf][(kstep*8 + mtile)*32 + lane][4]          (16B/lane  -> LDS.128)
//   Bf[buf][kstep*16*66 + ntile*66 + lane*2 + reg]   (8B/lane   -> LDS.64)
#define BSTRIDE 66

__device__ __forceinline__ uint32_t cvt_tf32(float f) {
    uint32_t r; asm("cvt.rna.tf32.f32 %0, %1;" : "=r"(r) : "f"(f)); return r;
}

__device__ __forceinline__ void mma1688(float* c, const uint32_t* a, const uint32_t* b) {
    asm volatile(
        "mma.sync.aligned.m16n8k8.row.col.f32.tf32.tf32.f32 "
        "{%0,%1,%2,%3}, {%4,%5,%6,%7}, {%8,%9}, {%0,%1,%2,%3};"
        : "+f"(c[0]), "+f"(c[1]), "+f"(c[2]), "+f"(c[3])
        : "r"(a[0]), "r"(a[1]), "r"(a[2]), "r"(a[3]), "r"(b[0]), "r"(b[1]));
}

template <int K, int NT, bool BIAS_RELU, bool A_HALF>
__device__ __forceinline__ void mma_body(const void* __restrict__ Avp,
                                         const float* __restrict__ B,
                                         const float* __restrict__ bias,
                                         __half* __restrict__ C) {
    __shared__ uint32_t Af[2][2048];
    __shared__ uint32_t Bf[2][2 * 16 * BSTRIDE];

    int tid  = threadIdx.x;
    int wid  = tid >> 5, lane = tid & 31;
    int wm   = wid >> 2, wn = wid & 3;        // 2x4 warp grid, 64x32 warp tile
    int rowBase = blockIdx.y * 128;
    int nBase   = blockIdx.x * 128;

    const float*  Abf = (const float*)Avp  + (size_t)rowBase * K;
    const __half* Abh = (const __half*)Avp + (size_t)rowBase * K;
    const float*  Bb  = B + nBase;

    float acc[4][4][4];
#pragma unroll
    for (int i = 0; i < 4; i++)
#pragma unroll
        for (int j = 0; j < 4; j++)
#pragma unroll
            for (int q = 0; q < 4; q++) acc[i][j][q] = 0.f;

    float4 sa[2], sb[2];

    auto ldStage = [&](int ch) {
#pragma unroll
        for (int it = 0; it < 2; it++) {
            int i = tid + it * 256;           // 0..511
            int row = i >> 2, k4 = (i & 3) << 2;
            if (A_HALF) {
                uint2 raw = *(const uint2*)(Abh + (size_t)row * K + ch * 16 + k4);
                float2 f0 = __half22float2(*(__half2*)&raw.x);
                float2 f1 = __half22float2(*(__half2*)&raw.y);
                sa[it] = make_float4(f0.x, f0.y, f1.x, f1.y);
            } else {
                sa[it] = *(const float4*)(Abf + (size_t)row * K + ch * 16 + k4);
            }
            int k = i >> 5, n4 = (i & 31) << 2;
            sb[it] = *(const float4*)(Bb + (size_t)(ch * 16 + k) * NT + n4);
        }
    };
    auto stStage = [&](uint32_t* af, uint32_t* bf) {
#pragma unroll
        for (int it = 0; it < 2; it++) {
            int i = tid + it * 256;
            {   // A element (row, k4+q)
                int row = i >> 2, k4 = (i & 3) << 2;
                int mtile = row >> 4, r = row & 15;
                const float* v = (const float*)&sa[it];
#pragma unroll
                for (int q = 0; q < 4; q++) {
                    int c = k4 + q, kstep = c >> 3, cc = c & 7;
                    int reg = ((r >> 3) & 1) | (((cc >> 2) & 1) << 1);
                    int ln  = (r & 7) * 4 + (cc & 3);
                    af[((kstep * 8 + mtile) * 32 + ln) * 4 + reg] = cvt_tf32(v[q]);
                }
            }
            {   // B element (k, n4+q)
                int k = i >> 5, n4 = (i & 31) << 2;
                int kstep = k >> 3, r = k & 7, reg = (r >> 2) & 1;
                const float* v = (const float*)&sb[it];
#pragma unroll
                for (int q = 0; q < 4; q++) {
                    int n = n4 + q, ntile = n >> 3;
                    int ln = (n & 7) * 4 + (r & 3);
                    bf[kstep * 16 * BSTRIDE + ntile * BSTRIDE + ln * 2 + reg] =
                        cvt_tf32(v[q]);
                }
            }
        }
    };

    const int nch = K >> 4;
    ldStage(0);
    stStage(Af[0], Bf[0]);
    __syncthreads();

#pragma unroll 1
    for (int ch = 0; ch < nch; ch++) {
        int buf = ch & 1;
        if (ch + 1 < nch) ldStage(ch + 1);    // LDG early, hide under mma

#pragma unroll
        for (int ks = 0; ks < 2; ks++) {
            uint32_t afr[4][4];
            uint32_t bfr[4][2];
#pragma unroll
            for (int i = 0; i < 4; i++) {
                int mtile = wm * 4 + i;
                *(uint4*)afr[i] =
                    *(const uint4*)&Af[buf][((ks * 8 + mtile) * 32 + lane) * 4];
            }
#pragma unroll
            for (int j = 0; j < 4; j++) {
                int ntile = wn * 4 + j;
                *(uint2*)bfr[j] =
                    *(const uint2*)&Bf[buf][ks * 16 * BSTRIDE + ntile * BSTRIDE + lane * 2];
            }
#pragma unroll
            for (int i = 0; i < 4; i++)
#pragma unroll
                for (int j = 0; j < 4; j++)
                    mma1688(acc[i][j], afr[i], bfr[j]);
        }

        if (ch + 1 < nch) stStage(Af[buf ^ 1], Bf[buf ^ 1]);
        __syncthreads();
    }

    // epilogue: fp16 output
    int crow = rowBase + wm * 64 + (lane >> 2);
    int ccol = nBase + wn * 32 + (lane & 3) * 2;
#pragma unroll
    for (int i = 0; i < 4; i++) {
#pragma unroll
        for (int j = 0; j < 4; j++) {
            int r0 = crow + i * 16, c0 = ccol + j * 8;
            float2 v0 = make_float2(acc[i][j][0], acc[i][j][1]);
            float2 v1 = make_float2(acc[i][j][2], acc[i][j][3]);
            if (BIAS_RELU) {
                float bx = bias[c0], by = bias[c0 + 1];
                v0.x = fmaxf(v0.x + bx, 0.f); v0.y = fmaxf(v0.y + by, 0.f);
                v1.x = fmaxf(v1.x + bx, 0.f); v1.y = fmaxf(v1.y + by, 0.f);
            }
            *(__half2*)&C[(size_t)r0 * NT + c0]       = __floats2half2_rn(v0.x, v0.y);
            *(__half2*)&C[(size_t)(r0 + 8) * NT + c0] = __floats2half2_rn(v1.x, v1.y);
        }
    }
}

// Wrappers: scratch symbols referenced from DEVICE code only.
__global__ __launch_bounds__(256)
void k_mma1(const float* __restrict__ W1, const float* __restrict__ b1) {
    mma_body<D_IN, D_HID, true, false>(g_xa, W1, b1, g_h1);
}
__global__ __launch_bounds__(256)
void k_mma2(const float* __restrict__ W2) {
    mma_body<D_HID, D_IN, false, true>(g_h1, W2, nullptr, g_y);
}

// ---------------- launch (kernel launches ONLY) -----------------------------
extern "C" void kernel_launch(void* const* d_in, const int* in_sizes, int n_in,
                              void* d_out, int out_size) {
    const float* x     = (const float*)d_in[0];
    const int*   ei    = (const int*)d_in[1];      // int32 edge_index [2, NE]
    const float* W1    = (const float*)d_in[2];
    const float* b1    = (const float*)d_in[3];
    const float* W2    = (const float*)d_in[4];
    const float* b2    = (const float*)d_in[5];
    const float* gamma = (const float*)d_in[6];
    const float* beta  = (const float*)d_in[7];
    float* out = (float*)d_out;

    // CSR build + x->fp16 conversion
    k_zero <<<(NN + 255) / 256, 256>>>();
    k_hist <<<(NE + 255) / 256, 256>>>(ei);
    k_cvt  <<<(NN * 32 + 255) / 256, 256>>>(x);
    k_scan <<<98, 1024>>>();
    k_final<<<(NN + 255) / 256, 256>>>();
    k_fill <<<(NE + 255) / 256, 256>>>(ei);

    // xa = A @ x  (fp16 gather, fp32 accum)
    k_agg1<<<(NN * 32) / 256, 256>>>();

    // h1 = relu(xa @ W1 + b1)   (tf32 mma, fp16 out)
    dim3 g1(D_HID / 128, NTILES);
    k_mma1<<<g1, 256>>>(W1, b1);

    // y = h1 @ W2               (tf32 mma, fp16 in/out)
    dim3 g2(D_IN / 128, NTILES);
    k_mma2<<<g2, 256>>>(W2);

    // out = LayerNorm(A @ y + b2)
    k_agg2<<<(NN * 32) / 256, 256>>>(out, b2, gamma, beta);
}

// round 8
// speedup vs baseline: 1.9945x; 1.2524x over previous
#include <cuda_runtime.h>
#include <cuda_fp16.h>
#include <cstdint>

#define NN   100000
#define NE   1600000
#define NPAD 100096          // 782 * 128
#define D_IN  128
#define D_HID 256
#define NTILES (NPAD / 128)  // 782

// ---------------- scratch (static __device__ arrays; device-code refs only) -
__device__ int   g_cnt[NN];
__device__ int   g_rowptr[NN + 1];
__device__ int   g_wp[NN];
__device__ __align__(8) int2 g_colw[NE];      // {src, __float_as_int(dinv[src])}
__device__ float g_dinv[NN];
__device__ int   g_bsum[128];
__device__ __align__(16) __half g_xh [(size_t)NN   * D_IN];   // x fp16
__device__ __align__(16) __half g_xa [(size_t)NPAD * D_IN];   // A@x fp16
__device__ __align__(16) __half g_h1 [(size_t)NPAD * D_HID];  // relu(xa@W1+b1)
__device__ __align__(16) __half g_y  [(size_t)NPAD * D_IN];   // h1@W2
__device__ __align__(16) __half g_w1h[D_IN * D_HID];
__device__ __align__(16) __half g_w2h[D_HID * D_IN];

// ---------------- fused convert + zero --------------------------------------
__global__ void k_cvtzero(const float* __restrict__ x,
                          const float* __restrict__ W1,
                          const float* __restrict__ W2) {
    int i = blockIdx.x * 256 + threadIdx.x;
    if (i < NN * 32) {
        float4 v = ((const float4*)x)[i];
        __half2 h0 = __floats2half2_rn(v.x, v.y);
        __half2 h1 = __floats2half2_rn(v.z, v.w);
        ((uint2*)g_xh)[i] = make_uint2(*(uint32_t*)&h0, *(uint32_t*)&h1);
    }
    if (i < NN) g_cnt[i] = 0;
    if (i < (D_IN * D_HID) / 4) {
        float4 a = ((const float4*)W1)[i];
        float4 b = ((const float4*)W2)[i];
        __half2 a0 = __floats2half2_rn(a.x, a.y), a1 = __floats2half2_rn(a.z, a.w);
        __half2 b0 = __floats2half2_rn(b.x, b.y), b1 = __floats2half2_rn(b.z, b.w);
        ((uint2*)g_w1h)[i] = make_uint2(*(uint32_t*)&a0, *(uint32_t*)&a1);
        ((uint2*)g_w2h)[i] = make_uint2(*(uint32_t*)&b0, *(uint32_t*)&b1);
    }
}

// ---------------- CSR build ------------------------------------------------
__global__ void k_hist(const int* __restrict__ ei) {
    int e = blockIdx.x * blockDim.x + threadIdx.x;
    if (e < NE) atomicAdd(&g_cnt[ei[NE + e]], 1);
}
__global__ void k_scan() {
    __shared__ int sh[1024];
    int i = blockIdx.x * 1024 + threadIdx.x;
    int v = (i < NN) ? g_cnt[i] : 0;
    sh[threadIdx.x] = v;
    __syncthreads();
    for (int off = 1; off < 1024; off <<= 1) {
        int t = (threadIdx.x >= off) ? sh[threadIdx.x - off] : 0;
        __syncthreads();
        sh[threadIdx.x] += t;
        __syncthreads();
    }
    if (i < NN) g_rowptr[i] = sh[threadIdx.x] - v;      // block-local exclusive
    if (threadIdx.x == 1023) g_bsum[blockIdx.x] = sh[1023];
}
__global__ void k_final() {    // block-sum scan folded in (redundant per block)
    __shared__ int shI[128];
    int t = threadIdx.x;
    if (t < 128) shI[t] = (t < 98) ? g_bsum[t] : 0;
    __syncthreads();
    for (int off = 1; off < 128; off <<= 1) {
        int u = (t >= off && t < 128) ? shI[t - off] : 0;
        __syncthreads();
        if (t < 128) shI[t] += u;
        __syncthreads();
    }
    int i = blockIdx.x * blockDim.x + t;
    if (i < NN) {
        int b = i >> 10;
        int base = (b == 0) ? 0 : shI[b - 1];
        int rp = g_rowptr[i] + base;
        g_rowptr[i] = rp;
        g_wp[i] = rp;
        g_dinv[i] = rsqrtf((float)(g_cnt[i] + 1));
    }
    if (i == 0) g_rowptr[NN] = NE;
}
__global__ void k_fill(const int* __restrict__ ei) {
    int e = blockIdx.x * blockDim.x + threadIdx.x;
    if (e < NE) {
        int s = ei[e];
        int d = ei[NE + e];
        int pos = atomicAdd(&g_wp[d], 1);
        g_colw[pos] = make_int2(s, __float_as_int(g_dinv[s]));
    }
}

// ---------------- aggregation: coalesced edge records + shfl broadcast -----
__device__ __forceinline__ float4 agg_row_h(const __half* __restrict__ X,
                                            int node, int lane) {
    const uint2* Xv = (const uint2*)X;
    float4 acc = make_float4(0.f, 0.f, 0.f, 0.f);
    int r0 = g_rowptr[node], r1 = g_rowptr[node + 1];
    float di = g_dinv[node];

    for (int base = r0; base < r1; base += 32) {
        int n = r1 - base; if (n > 32) n = 32;
        int2 cw = g_colw[base + (lane < n ? lane : 0)];   // coalesced
#pragma unroll 1
        for (int t = 0; t < n; t++) {
            int   s = __shfl_sync(0xffffffffu, cw.x, t);
            float w = __int_as_float(__shfl_sync(0xffffffffu, cw.y, t));
            uint2 raw = Xv[(size_t)s * 32 + lane];        // independent loads
            float2 f0 = __half22float2(*(__half2*)&raw.x);
            float2 f1 = __half22float2(*(__half2*)&raw.y);
            acc.x += f0.x * w; acc.y += f0.y * w;
            acc.z += f1.x * w; acc.w += f1.y * w;
        }
    }
    uint2 raw = Xv[(size_t)node * 32 + lane];             // self-loop
    float2 f0 = __half22float2(*(__half2*)&raw.x);
    float2 f1 = __half22float2(*(__half2*)&raw.y);
    acc.x = (acc.x + f0.x * di) * di;
    acc.y = (acc.y + f0.y * di) * di;
    acc.z = (acc.z + f1.x * di) * di;
    acc.w = (acc.w + f1.y * di) * di;
    return acc;
}

__global__ void k_agg1() {
    int gw   = (blockIdx.x * blockDim.x + threadIdx.x) >> 5;
    int lane = threadIdx.x & 31;
    if (gw >= NN) return;
    float4 a = agg_row_h(g_xh, gw, lane);
    __half2 h0 = __floats2half2_rn(a.x, a.y);
    __half2 h1 = __floats2half2_rn(a.z, a.w);
    ((uint2*)g_xa)[(size_t)gw * 32 + lane] =
        make_uint2(*(uint32_t*)&h0, *(uint32_t*)&h1);
}

__global__ void k_agg2(float* __restrict__ out,
                       const float* __restrict__ bias,
                       const float* __restrict__ gamma,
                       const float* __restrict__ beta) {
    int gw   = (blockIdx.x * blockDim.x + threadIdx.x) >> 5;
    int lane = threadIdx.x & 31;
    if (gw >= NN) return;
    float4 acc = agg_row_h(g_y, gw, lane);

    float4 bb = ((const float4*)bias)[lane];
    acc.x += bb.x; acc.y += bb.y; acc.z += bb.z; acc.w += bb.w;

    float s = acc.x + acc.y + acc.z + acc.w;
#pragma unroll
    for (int o = 16; o; o >>= 1) s += __shfl_xor_sync(0xffffffffu, s, o);
    float mu = s * (1.f / 128.f);

    float d0 = acc.x - mu, d1 = acc.y - mu, d2 = acc.z - mu, d3 = acc.w - mu;
    float ss = d0 * d0 + d1 * d1 + d2 * d2 + d3 * d3;
#pragma unroll
    for (int o = 16; o; o >>= 1) ss += __shfl_xor_sync(0xffffffffu, ss, o);
    float rs = rsqrtf(ss * (1.f / 128.f) + 1e-5f);

    float4 g  = ((const float4*)gamma)[lane];
    float4 be = ((const float4*)beta)[lane];
    float4 o4;
    o4.x = d0 * rs * g.x + be.x;
    o4.y = d1 * rs * g.y + be.y;
    o4.z = d2 * rs * g.z + be.z;
    o4.w = d3 * rs * g.w + be.w;
    ((float4*)out)[(size_t)gw * 32 + lane] = o4;
}

// ---------------- fp16 mma.sync GEMM with ldmatrix --------------------------
// C[128,NT-tile] = A[128,K] @ B[K,NT]; all fp16, fp32 accum, fp16 out.
// SMEM: A chunk 128x32 fp16 rows 64B, swizzle c16^=(r>>1)&3.
//       B chunk 32xNTtile(128) fp16 rows 256B, swizzle c16^=(k&7).
__device__ __forceinline__ uint32_t smem_u32(const void* p) {
    uint32_t a;
    asm("{ .reg .u64 t; cvta.to.shared.u64 t, %1; cvt.u32.u64 %0, t; }"
        : "=r"(a) : "l"(p));
    return a;
}
__device__ __forceinline__ void ldsm_x4(uint32_t* r, uint32_t addr) {
    asm volatile("ldmatrix.sync.aligned.m8n8.x4.shared.b16 {%0,%1,%2,%3}, [%4];"
        : "=r"(r[0]), "=r"(r[1]), "=r"(r[2]), "=r"(r[3]) : "r"(addr));
}
__device__ __forceinline__ void ldsm_x2t(uint32_t* r, uint32_t addr) {
    asm volatile("ldmatrix.sync.aligned.m8n8.x2.trans.shared.b16 {%0,%1}, [%2];"
        : "=r"(r[0]), "=r"(r[1]) : "r"(addr));
}
__device__ __forceinline__ void mma_f16(float* c, const uint32_t* a, const uint32_t* b) {
    asm volatile(
        "mma.sync.aligned.m16n8k16.row.col.f32.f16.f16.f32 "
        "{%0,%1,%2,%3}, {%4,%5,%6,%7}, {%8,%9}, {%0,%1,%2,%3};"
        : "+f"(c[0]), "+f"(c[1]), "+f"(c[2]), "+f"(c[3])
        : "r"(a[0]), "r"(a[1]), "r"(a[2]), "r"(a[3]), "r"(b[0]), "r"(b[1]));
}

template <int K, int NT, bool BIAS_RELU>
__device__ __forceinline__ void mma_body_h(const __half* __restrict__ A,
                                           const __half* __restrict__ B,
                                           const float* __restrict__ bias,
                                           __half* __restrict__ C) {
    __shared__ __align__(16) char Asm[2][8192];
    __shared__ __align__(16) char Bsm[2][8192];

    int tid = threadIdx.x, wid = tid >> 5, lane = tid & 31;
    int wm = wid >> 2, wn = wid & 3;          // 2x4 warps, 64x32 warp tile
    int rowBase = blockIdx.y * 128;
    int nBase   = blockIdx.x * 128;

    const __half* Ab = A + (size_t)rowBase * K;
    const __half* Bb = B + nBase;

    float acc[4][4][4];
#pragma unroll
    for (int i = 0; i < 4; i++)
#pragma unroll
        for (int j = 0; j < 4; j++)
#pragma unroll
            for (int q = 0; q < 4; q++) acc[i][j][q] = 0.f;

    uint4 sa[2], sb[2];
    auto ldStage = [&](int ch) {
#pragma unroll
        for (int it = 0; it < 2; it++) {
            int u = tid + it * 256;
            sa[it] = *(const uint4*)(Ab + (size_t)(u >> 2) * K + ch * 32 + (u & 3) * 8);
            sb[it] = *(const uint4*)(Bb + (size_t)(ch * 32 + (u >> 4)) * NT + (u & 15) * 8);
        }
    };
    auto stStage = [&](int buf) {
#pragma unroll
        for (int it = 0; it < 2; it++) {
            int u = tid + it * 256;
            int r = u >> 2, c16 = u & 3;
            *(uint4*)(Asm[buf] + r * 64 + ((c16 ^ ((r >> 1) & 3)) << 4)) = sa[it];
            int k = u >> 4, d16 = u & 15;
            *(uint4*)(Bsm[buf] + k * 256 + ((d16 ^ (k & 7)) << 4)) = sb[it];
        }
    };

    const int nch = K >> 5;
    ldStage(0);
    stStage(0);
    __syncthreads();

    // per-lane ldmatrix address components
    int aG  = lane >> 3;                       // 0..3
    int aRl = (aG & 1) * 8 + (lane & 7);       // row within 16
    int aCo = aG >> 1;                         // c16 offset 0/1
    int bK  = lane & 15;                       // k within 16 (x2 uses 16 lanes)

#pragma unroll 1
    for (int ch = 0; ch < nch; ch++) {
        int buf = ch & 1;
        if (ch + 1 < nch) ldStage(ch + 1);

        uint32_t aBase = smem_u32(Asm[buf]);
        uint32_t bBase = smem_u32(Bsm[buf]);
#pragma unroll
        for (int ks = 0; ks < 2; ks++) {
            uint32_t af[4][4], bf[4][2];
#pragma unroll
            for (int i = 0; i < 4; i++) {
                int r   = (wm * 4 + i) * 16 + aRl;
                int c16 = ks * 2 + aCo;
                ldsm_x4(af[i], aBase + r * 64 + ((c16 ^ ((r >> 1) & 3)) << 4));
            }
#pragma unroll
            for (int j = 0; j < 4; j++) {
                int ntile = wn * 4 + j;
                int k = ks * 16 + bK;
                ldsm_x2t(bf[j], bBase + k * 256 + ((ntile ^ (k & 7)) << 4));
            }
#pragma unroll
            for (int i = 0; i < 4; i++)
#pragma unroll
                for (int j = 0; j < 4; j++)
                    mma_f16(acc[i][j], af[i], bf[j]);
        }

        if (ch + 1 < nch) stStage(buf ^ 1);
        __syncthreads();
    }

    // epilogue (fp16 out)
    int crow = rowBase + wm * 64 + (lane >> 2);
    int ccol = nBase + wn * 32 + (lane & 3) * 2;
#pragma unroll
    for (int i = 0; i < 4; i++) {
#pragma unroll
        for (int j = 0; j < 4; j++) {
            int r0 = crow + i * 16, c0 = ccol + j * 8;
            float2 v0 = make_float2(acc[i][j][0], acc[i][j][1]);
            float2 v1 = make_float2(acc[i][j][2], acc[i][j][3]);
            if (BIAS_RELU) {
                float bx = bias[c0], by = bias[c0 + 1];
                v0.x = fmaxf(v0.x + bx, 0.f); v0.y = fmaxf(v0.y + by, 0.f);
                v1.x = fmaxf(v1.x + bx, 0.f); v1.y = fmaxf(v1.y + by, 0.f);
            }
            *(__half2*)&C[(size_t)r0 * NT + c0]       = __floats2half2_rn(v0.x, v0.y);
            *(__half2*)&C[(size_t)(r0 + 8) * NT + c0] = __floats2half2_rn(v1.x, v1.y);
        }
    }
}

__global__ __launch_bounds__(256)
void k_mma1(const float* __restrict__ b1) {
    mma_body_h<D_IN, D_HID, true>(g_xa, g_w1h, b1, g_h1);
}
__global__ __launch_bounds__(256)
void k_mma2() {
    mma_body_h<D_HID, D_IN, false>(g_h1, g_w2h, nullptr, g_y);
}

// ---------------- launch (kernel launches ONLY) -----------------------------
extern "C" void kernel_launch(void* const* d_in, const int* in_sizes, int n_in,
                              void* d_out, int out_size) {
    const float* x     = (const float*)d_in[0];
    const int*   ei    = (const int*)d_in[1];      // int32 edge_index [2, NE]
    const float* W1    = (const float*)d_in[2];
    const float* b1    = (const float*)d_in[3];
    const float* W2    = (const float*)d_in[4];
    const float* b2    = (const float*)d_in[5];
    const float* gamma = (const float*)d_in[6];
    const float* beta  = (const float*)d_in[7];
    float* out = (float*)d_out;

    k_cvtzero<<<(NN * 32 + 255) / 256, 256>>>(x, W1, W2);
    k_hist   <<<(NE + 255) / 256, 256>>>(ei);
    k_scan   <<<98, 1024>>>();
    k_final  <<<(NN + 255) / 256, 256>>>();
    k_fill   <<<(NE + 255) / 256, 256>>>(ei);

    // xa = A @ x  (fp16 gather, fp32 accum, fp16 out)
    k_agg1<<<(NN * 32) / 256, 256>>>();

    // h1 = relu(xa @ W1 + b1)   (fp16 mma + ldmatrix)
    dim3 g1(D_HID / 128, NTILES);
    k_mma1<<<g1, 256>>>(b1);

    // y = h1 @ W2
    dim3 g2(D_IN / 128, NTILES);
    k_mma2<<<g2, 256>>>();

    // out = LayerNorm(A @ y + b2)
    k_agg2<<<(NN * 32) / 256, 256>>>(out, b2, gamma, beta);
}

// round 9
// speedup vs baseline: 2.1564x; 1.0812x over previous
#include <cuda_runtime.h>
#include <cuda_fp16.h>
#include <cstdint>

#define NN   100000
#define NE   1600000
#define NPAD 100096          // 782 * 128
#define D_IN  128
#define D_HID 256
#define NTILES (NPAD / 128)  // 782

// ---------------- scratch (static __device__ arrays; device-code refs only) -
__device__ int   g_cnt[NN];
__device__ int   g_rowptr[NN + 1];
__device__ int   g_wp[NN];
__device__ __align__(8) int2 g_colw[NE];      // {src, __float_as_int(dinv[src])}
__device__ float g_dinv[NN];
__device__ int   g_bsum[128];
__device__ __align__(16) __half g_xh [(size_t)NN   * D_IN];   // x fp16
__device__ __align__(16) __half g_xa [(size_t)NPAD * D_IN];   // A@x fp16
__device__ __align__(16) __half g_h1 [(size_t)NPAD * D_HID];  // relu(xa@W1+b1)
__device__ __align__(16) __half g_y  [(size_t)NPAD * D_IN];   // h1@W2
__device__ __align__(16) __half g_w1h[D_IN * D_HID];
__device__ __align__(16) __half g_w2h[D_HID * D_IN];

// ---------------- fused convert + zero --------------------------------------
__global__ void k_cvtzero(const float* __restrict__ x,
                          const float* __restrict__ W1,
                          const float* __restrict__ W2) {
    int i = blockIdx.x * 256 + threadIdx.x;
    if (i < NN * 32) {
        float4 v = ((const float4*)x)[i];
        __half2 h0 = __floats2half2_rn(v.x, v.y);
        __half2 h1 = __floats2half2_rn(v.z, v.w);
        ((uint2*)g_xh)[i] = make_uint2(*(uint32_t*)&h0, *(uint32_t*)&h1);
    }
    if (i < NN) g_cnt[i] = 0;
    if (i < (D_IN * D_HID) / 4) {
        float4 a = ((const float4*)W1)[i];
        float4 b = ((const float4*)W2)[i];
        __half2 a0 = __floats2half2_rn(a.x, a.y), a1 = __floats2half2_rn(a.z, a.w);
        __half2 b0 = __floats2half2_rn(b.x, b.y), b1 = __floats2half2_rn(b.z, b.w);
        ((uint2*)g_w1h)[i] = make_uint2(*(uint32_t*)&a0, *(uint32_t*)&a1);
        ((uint2*)g_w2h)[i] = make_uint2(*(uint32_t*)&b0, *(uint32_t*)&b1);
    }
}

// ---------------- CSR build ------------------------------------------------
__global__ void k_hist(const int* __restrict__ ei) {
    int e = blockIdx.x * blockDim.x + threadIdx.x;
    if (e < NE) atomicAdd(&g_cnt[ei[NE + e]], 1);
}
__global__ void k_scan() {
    __shared__ int sh[1024];
    int i = blockIdx.x * 1024 + threadIdx.x;
    int v = (i < NN) ? g_cnt[i] : 0;
    sh[threadIdx.x] = v;
    __syncthreads();
    for (int off = 1; off < 1024; off <<= 1) {
        int t = (threadIdx.x >= off) ? sh[threadIdx.x - off] : 0;
        __syncthreads();
        sh[threadIdx.x] += t;
        __syncthreads();
    }
    if (i < NN) g_rowptr[i] = sh[threadIdx.x] - v;      // block-local exclusive
    if (threadIdx.x == 1023) g_bsum[blockIdx.x] = sh[1023];
}
__global__ void k_final() {    // block-sum scan folded in (redundant per block)
    __shared__ int shI[128];
    int t = threadIdx.x;
    if (t < 128) shI[t] = (t < 98) ? g_bsum[t] : 0;
    __syncthreads();
    for (int off = 1; off < 128; off <<= 1) {
        int u = (t >= off && t < 128) ? shI[t - off] : 0;
        __syncthreads();
        if (t < 128) shI[t] += u;
        __syncthreads();
    }
    int i = blockIdx.x * blockDim.x + t;
    if (i < NN) {
        int b = i >> 10;
        int base = (b == 0) ? 0 : shI[b - 1];
        int rp = g_rowptr[i] + base;
        g_rowptr[i] = rp;
        g_wp[i] = rp;
        g_dinv[i] = rsqrtf((float)(g_cnt[i] + 1));
    }
    if (i == 0) g_rowptr[NN] = NE;
}
__global__ void k_fill(const int* __restrict__ ei) {
    int e = blockIdx.x * blockDim.x + threadIdx.x;
    if (e < NE) {
        int s = ei[e];
        int d = ei[NE + e];
        int pos = atomicAdd(&g_wp[d], 1);
        g_colw[pos] = make_int2(s, __float_as_int(g_dinv[s]));
    }
}

// ---------------- aggregation: coalesced edge records, MLP-4 gather --------
__device__ __forceinline__ void fma_row(float4& acc, uint2 raw, float w) {
    float2 f0 = __half22float2(*(__half2*)&raw.x);
    float2 f1 = __half22float2(*(__half2*)&raw.y);
    acc.x += f0.x * w; acc.y += f0.y * w;
    acc.z += f1.x * w; acc.w += f1.y * w;
}

__device__ __forceinline__ float4 agg_row_h(const __half* __restrict__ X,
                                            int node, int lane) {
    const uint2* Xv = (const uint2*)X;
    float4 acc = make_float4(0.f, 0.f, 0.f, 0.f);
    int r0 = g_rowptr[node], r1 = g_rowptr[node + 1];
    float di = g_dinv[node];

    for (int base = r0; base < r1; base += 32) {
        int n = r1 - base; if (n > 32) n = 32;
        int2 cw = g_colw[base + (lane < n ? lane : 0)];   // coalesced
        int t = 0;
#pragma unroll 1
        for (; t + 4 <= n; t += 4) {                      // MLP=4: 4 indep LDGs
            int   s0 = __shfl_sync(0xffffffffu, cw.x, t);
            int   s1 = __shfl_sync(0xffffffffu, cw.x, t + 1);
            int   s2 = __shfl_sync(0xffffffffu, cw.x, t + 2);
            int   s3 = __shfl_sync(0xffffffffu, cw.x, t + 3);
            float w0 = __int_as_float(__shfl_sync(0xffffffffu, cw.y, t));
            float w1 = __int_as_float(__shfl_sync(0xffffffffu, cw.y, t + 1));
            float w2 = __int_as_float(__shfl_sync(0xffffffffu, cw.y, t + 2));
            float w3 = __int_as_float(__shfl_sync(0xffffffffu, cw.y, t + 3));
            uint2 q0 = Xv[(size_t)s0 * 32 + lane];
            uint2 q1 = Xv[(size_t)s1 * 32 + lane];
            uint2 q2 = Xv[(size_t)s2 * 32 + lane];
            uint2 q3 = Xv[(size_t)s3 * 32 + lane];
            fma_row(acc, q0, w0);
            fma_row(acc, q1, w1);
            fma_row(acc, q2, w2);
            fma_row(acc, q3, w3);
        }
#pragma unroll 1
        for (; t < n; t++) {
            int   s = __shfl_sync(0xffffffffu, cw.x, t);
            float w = __int_as_float(__shfl_sync(0xffffffffu, cw.y, t));
            fma_row(acc, Xv[(size_t)s * 32 + lane], w);
        }
    }
    uint2 raw = Xv[(size_t)node * 32 + lane];             // self-loop
    float2 f0 = __half22float2(*(__half2*)&raw.x);
    float2 f1 = __half22float2(*(__half2*)&raw.y);
    acc.x = (acc.x + f0.x * di) * di;
    acc.y = (acc.y + f0.y * di) * di;
    acc.z = (acc.z + f1.x * di) * di;
    acc.w = (acc.w + f1.y * di) * di;
    return acc;
}

__global__ void k_agg1() {
    int gw   = (blockIdx.x * blockDim.x + threadIdx.x) >> 5;
    int lane = threadIdx.x & 31;
    if (gw >= NN) return;
    float4 a = agg_row_h(g_xh, gw, lane);
    __half2 h0 = __floats2half2_rn(a.x, a.y);
    __half2 h1 = __floats2half2_rn(a.z, a.w);
    ((uint2*)g_xa)[(size_t)gw * 32 + lane] =
        make_uint2(*(uint32_t*)&h0, *(uint32_t*)&h1);
}

__global__ void k_agg2(float* __restrict__ out,
                       const float* __restrict__ bias,
                       const float* __restrict__ gamma,
                       const float* __restrict__ beta) {
    int gw   = (blockIdx.x * blockDim.x + threadIdx.x) >> 5;
    int lane = threadIdx.x & 31;
    if (gw >= NN) return;
    float4 acc = agg_row_h(g_y, gw, lane);

    float4 bb = ((const float4*)bias)[lane];
    acc.x += bb.x; acc.y += bb.y; acc.z += bb.z; acc.w += bb.w;

    float s = acc.x + acc.y + acc.z + acc.w;
#pragma unroll
    for (int o = 16; o; o >>= 1) s += __shfl_xor_sync(0xffffffffu, s, o);
    float mu = s * (1.f / 128.f);

    float d0 = acc.x - mu, d1 = acc.y - mu, d2 = acc.z - mu, d3 = acc.w - mu;
    float ss = d0 * d0 + d1 * d1 + d2 * d2 + d3 * d3;
#pragma unroll
    for (int o = 16; o; o >>= 1) ss += __shfl_xor_sync(0xffffffffu, ss, o);
    float rs = rsqrtf(ss * (1.f / 128.f) + 1e-5f);

    float4 g  = ((const float4*)gamma)[lane];
    float4 be = ((const float4*)beta)[lane];
    float4 o4;
    o4.x = d0 * rs * g.x + be.x;
    o4.y = d1 * rs * g.y + be.y;
    o4.z = d2 * rs * g.z + be.z;
    o4.w = d3 * rs * g.w + be.w;
    ((float4*)out)[(size_t)gw * 32 + lane] = o4;
}

// ---------------- fp16 mma.sync GEMM with ldmatrix --------------------------
__device__ __forceinline__ uint32_t smem_u32(const void* p) {
    uint32_t a;
    asm("{ .reg .u64 t; cvta.to.shared.u64 t, %1; cvt.u32.u64 %0, t; }"
        : "=r"(a) : "l"(p));
    return a;
}
__device__ __forceinline__ void ldsm_x4(uint32_t* r, uint32_t addr) {
    asm volatile("ldmatrix.sync.aligned.m8n8.x4.shared.b16 {%0,%1,%2,%3}, [%4];"
        : "=r"(r[0]), "=r"(r[1]), "=r"(r[2]), "=r"(r[3]) : "r"(addr));
}
__device__ __forceinline__ void ldsm_x2t(uint32_t* r, uint32_t addr) {
    asm volatile("ldmatrix.sync.aligned.m8n8.x2.trans.shared.b16 {%0,%1}, [%2];"
        : "=r"(r[0]), "=r"(r[1]) : "r"(addr));
}
__device__ __forceinline__ void mma_f16(float* c, const uint32_t* a, const uint32_t* b) {
    asm volatile(
        "mma.sync.aligned.m16n8k16.row.col.f32.f16.f16.f32 "
        "{%0,%1,%2,%3}, {%4,%5,%6,%7}, {%8,%9}, {%0,%1,%2,%3};"
        : "+f"(c[0]), "+f"(c[1]), "+f"(c[2]), "+f"(c[3])
        : "r"(a[0]), "r"(a[1]), "r"(a[2]), "r"(a[3]), "r"(b[0]), "r"(b[1]));
}

template <int K, int NT, bool BIAS_RELU>
__device__ __forceinline__ void mma_body_h(const __half* __restrict__ A,
                                           const __half* __restrict__ B,
                                           const float* __restrict__ bias,
                                           __half* __restrict__ C) {
    __shared__ __align__(16) char Asm[2][8192];
    __shared__ __align__(16) char Bsm[2][8192];

    int tid = threadIdx.x, wid = tid >> 5, lane = tid & 31;
    int wm = wid >> 2, wn = wid & 3;          // 2x4 warps, 64x32 warp tile
    int rowBase = blockIdx.y * 128;
    int nBase   = blockIdx.x * 128;

    const __half* Ab = A + (size_t)rowBase * K;
    const __half* Bb = B + nBase;

    float acc[4][4][4];
#pragma unroll
    for (int i = 0; i < 4; i++)
#pragma unroll
        for (int j = 0; j < 4; j++)
#pragma unroll
            for (int q = 0; q < 4; q++) acc[i][j][q] = 0.f;

    uint4 sa[2], sb[2];
    auto ldStage = [&](int ch) {
#pragma unroll
        for (int it = 0; it < 2; it++) {
            int u = tid + it * 256;
            sa[it] = *(const uint4*)(Ab + (size_t)(u >> 2) * K + ch * 32 + (u & 3) * 8);
            sb[it] = *(const uint4*)(Bb + (size_t)(ch * 32 + (u >> 4)) * NT + (u & 15) * 8);
        }
    };
    auto stStage = [&](int buf) {
#pragma unroll
        for (int it = 0; it < 2; it++) {
            int u = tid + it * 256;
            int r = u >> 2, c16 = u & 3;
            *(uint4*)(Asm[buf] + r * 64 + ((c16 ^ ((r >> 1) & 3)) << 4)) = sa[it];
            int k = u >> 4, d16 = u & 15;
            *(uint4*)(Bsm[buf] + k * 256 + ((d16 ^ (k & 7)) << 4)) = sb[it];
        }
    };

    const int nch = K >> 5;
    ldStage(0);
    stStage(0);
    __syncthreads();

    int aG  = lane >> 3;
    int aRl = (aG & 1) * 8 + (lane & 7);
    int aCo = aG >> 1;
    int bK  = lane & 15;

#pragma unroll 1
    for (int ch = 0; ch < nch; ch++) {
        int buf = ch & 1;
        if (ch + 1 < nch) ldStage(ch + 1);

        uint32_t aBase = smem_u32(Asm[buf]);
        uint32_t bBase = smem_u32(Bsm[buf]);
#pragma unroll
        for (int ks = 0; ks < 2; ks++) {
            uint32_t af[4][4], bf[4][2];
#pragma unroll
            for (int i = 0; i < 4; i++) {
                int r   = (wm * 4 + i) * 16 + aRl;
                int c16 = ks * 2 + aCo;
                ldsm_x4(af[i], aBase + r * 64 + ((c16 ^ ((r >> 1) & 3)) << 4));
            }
#pragma unroll
            for (int j = 0; j < 4; j++) {
                int ntile = wn * 4 + j;
                int k = ks * 16 + bK;
                ldsm_x2t(bf[j], bBase + k * 256 + ((ntile ^ (k & 7)) << 4));
            }
#pragma unroll
            for (int i = 0; i < 4; i++)
#pragma unroll
                for (int j = 0; j < 4; j++)
                    mma_f16(acc[i][j], af[i], bf[j]);
        }

        if (ch + 1 < nch) stStage(buf ^ 1);
        __syncthreads();
    }

    // epilogue (fp16 out)
    int crow = rowBase + wm * 64 + (lane >> 2);
    int ccol = nBase + wn * 32 + (lane & 3) * 2;
#pragma unroll
    for (int i = 0; i < 4; i++) {
#pragma unroll
        for (int j = 0; j < 4; j++) {
            int r0 = crow + i * 16, c0 = ccol + j * 8;
            float2 v0 = make_float2(acc[i][j][0], acc[i][j][1]);
            float2 v1 = make_float2(acc[i][j][2], acc[i][j][3]);
            if (BIAS_RELU) {
                float bx = bias[c0], by = bias[c0 + 1];
                v0.x = fmaxf(v0.x + bx, 0.f); v0.y = fmaxf(v0.y + by, 0.f);
                v1.x = fmaxf(v1.x + bx, 0.f); v1.y = fmaxf(v1.y + by, 0.f);
            }
            *(__half2*)&C[(size_t)r0 * NT + c0]       = __floats2half2_rn(v0.x, v0.y);
            *(__half2*)&C[(size_t)(r0 + 8) * NT + c0] = __floats2half2_rn(v1.x, v1.y);
        }
    }
}

__global__ __launch_bounds__(256)
void k_mma1(const float* __restrict__ b1) {
    mma_body_h<D_IN, D_HID, true>(g_xa, g_w1h, b1, g_h1);
}
__global__ __launch_bounds__(256)
void k_mma2() {
    mma_body_h<D_HID, D_IN, false>(g_h1, g_w2h, nullptr, g_y);
}

// ---------------- launch (kernel launches ONLY) -----------------------------
extern "C" void kernel_launch(void* const* d_in, const int* in_sizes, int n_in,
                              void* d_out, int out_size) {
    const float* x     = (const float*)d_in[0];
    const int*   ei    = (const int*)d_in[1];      // int32 edge_index [2, NE]
    const float* W1    = (const float*)d_in[2];
    const float* b1    = (const float*)d_in[3];
    const float* W2    = (const float*)d_in[4];
    const float* b2    = (const float*)d_in[5];
    const float* gamma = (const float*)d_in[6];
    const float* beta  = (const float*)d_in[7];
    float* out = (float*)d_out;

    k_cvtzero<<<(NN * 32 + 255) / 256, 256>>>(x, W1, W2);
    k_hist   <<<(NE + 255) / 256, 256>>>(ei);
    k_scan   <<<98, 1024>>>();
    k_final  <<<(NN + 255) / 256, 256>>>();
    k_fill   <<<(NE + 255) / 256, 256>>>(ei);

    // xa = A @ x  (fp16 gather, MLP-4, fp32 accum, fp16 out)
    k_agg1<<<(NN * 32) / 256, 256>>>();

    // h1 = relu(xa @ W1 + b1)   (fp16 mma + ldmatrix)
    dim3 g1(D_HID / 128, NTILES);
    k_mma1<<<g1, 256>>>(b1);

    // y = h1 @ W2
    dim3 g2(D_IN / 128, NTILES);
    k_mma2<<<g2, 256>>>();

    // out = LayerNorm(A @ y + b2)
    k_agg2<<<(NN * 32) / 256, 256>>>(out, b2, gamma, beta);
}